// round 5
// baseline (speedup 1.0000x reference)
#include <cuda_runtime.h>
#include <cstdint>

// GestureClassifier: 2 stacks x 5-layer LSTM (H=32, B=16384, T=20) + FC(1280->128 relu ->5)
// Strategy: one thread per batch element, f32x2 packed FMAs (reduction-dim packing),
// weights broadcast from shared, inter-layer handoff via [t][h][B] global scratch.

#define BB 16384
#define TT 20
#define HH 32

typedef unsigned long long ull;

static __device__ float d_scr[2][2][(size_t)TT * HH * BB];       // [stack][parity][t*32+h][b]
static __device__ float d_fcT[(size_t)2 * TT * HH * BB];         // [k=0..1279][b]  (A^T for FC)
static __device__ float d_wt[1280 * 128];                        // fc1_w transposed [k][o]

// ---------------- f32x2 helpers ----------------
__device__ __forceinline__ ull pk2(float lo, float hi) {
    ull r; asm("mov.b64 %0, {%1, %2};" : "=l"(r) : "f"(lo), "f"(hi)); return r;
}
__device__ __forceinline__ void up2(ull v, float& lo, float& hi) {
    asm("mov.b64 {%0, %1}, %2;" : "=f"(lo), "=f"(hi) : "l"(v));
}
__device__ __forceinline__ ull fma2(ull a, ull b, ull c) {
    ull d; asm("fma.rn.f32x2 %0, %1, %2, %3;" : "=l"(d) : "l"(a), "l"(b), "l"(c)); return d;
}
__device__ __forceinline__ ull add2(ull a, ull b) {
    ull d; asm("add.rn.f32x2 %0, %1, %2;" : "=l"(d) : "l"(a), "l"(b)); return d;
}

__device__ __forceinline__ float sigf(float x) {
    return __fdividef(1.f, 1.f + __expf(-x));
}
__device__ __forceinline__ float tanhfast(float x) {
    return __fdividef(2.f, 1.f + __expf(-2.f * x)) - 1.f;
}

// ---------------- LSTM ----------------
// gate preactivation for one gate row: bias + Wih_row . x + Whh_row . h
// NXP = number of f32x2 pairs of the input vector (16 for H=32 input, 2 for padded D=3)
template <int NXP>
__device__ __forceinline__ float gate_dot(const float* wi_row, const float* wh_row,
                                          const ull* xv, const ull* hv, float bias) {
    const ulonglong2* wi = reinterpret_cast<const ulonglong2*>(wi_row);
    const ulonglong2* wh = reinterpret_cast<const ulonglong2*>(wh_row);
    ull a0 = 0, a1 = 0, a2 = 0, a3 = 0;
#pragma unroll
    for (int q = 0; q < NXP / 2; q++) {
        ulonglong2 w = wi[q];
        a0 = fma2(w.x, xv[2 * q], a0);
        a1 = fma2(w.y, xv[2 * q + 1], a1);
    }
#pragma unroll
    for (int q = 0; q < 8; q++) {
        ulonglong2 w = wh[q];
        a2 = fma2(w.x, hv[2 * q], a2);
        a3 = fma2(w.y, hv[2 * q + 1], a3);
    }
    ull s = add2(add2(a0, a2), add2(a1, a3));
    float lo, hi; up2(s, lo, hi);
    return bias + lo + hi;
}

// One LSTM layer for one batch element.
//  FIRST: x from raw input [b][t][3];  else: x from src[t*32+k][b]
//  dst[t*32+j][b] receives h; h for step t is reloaded from dst[t-1] (same thread).
template <int NXP, bool FIRST>
__device__ __forceinline__ void run_layer(int b, const float* __restrict__ in3,
                                          const float* __restrict__ src,
                                          float* __restrict__ dst,
                                          const float* sWi, const float* sWh,
                                          const float* sB, float* csrow) {
    ull xv[16], hv[16];
#pragma unroll
    for (int p = 0; p < 16; p++) { xv[p] = 0ull; hv[p] = 0ull; }
#pragma unroll
    for (int j = 0; j < 32; j++) csrow[j * 64] = 0.f;

#pragma unroll 1
    for (int t = 0; t < TT; t++) {
        if constexpr (FIRST) {
            const float* p = in3 + ((size_t)b * TT + t) * 3;
            xv[0] = pk2(p[0], p[1]);
            xv[1] = pk2(p[2], 0.f);
        } else {
            const float* s0 = src + (size_t)t * HH * BB + b;
#pragma unroll
            for (int p = 0; p < 16; p++)
                xv[p] = pk2(s0[(size_t)(2 * p) * BB], s0[(size_t)(2 * p + 1) * BB]);
        }
        if (t > 0) {
            const float* h0 = dst + (size_t)(t - 1) * HH * BB + b;
#pragma unroll
            for (int p = 0; p < 16; p++)
                hv[p] = pk2(h0[(size_t)(2 * p) * BB], h0[(size_t)(2 * p + 1) * BB]);
        }
        float* o0 = dst + (size_t)t * HH * BB + b;
#pragma unroll 2
        for (int j = 0; j < 32; j++) {
            float gi = gate_dot<NXP>(sWi + j * 32,          sWh + j * 32,          xv, hv, sB[j]);
            float gf = gate_dot<NXP>(sWi + (32 + j) * 32,   sWh + (32 + j) * 32,   xv, hv, sB[32 + j]);
            float gg = gate_dot<NXP>(sWi + (64 + j) * 32,   sWh + (64 + j) * 32,   xv, hv, sB[64 + j]);
            float go = gate_dot<NXP>(sWi + (96 + j) * 32,   sWh + (96 + j) * 32,   xv, hv, sB[96 + j]);
            float ig = sigf(gi);
            float fg = sigf(gf);
            float gv = tanhfast(gg);
            float og = sigf(go);
            float c = fg * csrow[j * 64] + ig * gv;
            csrow[j * 64] = c;
            o0[(size_t)j * BB] = og * tanhfast(c);
        }
    }
}

__global__ void __launch_bounds__(64) lstm_kernel(
    const float* __restrict__ accel, const float* __restrict__ gyro,
    const float* __restrict__ aWih0, const float* __restrict__ aWihR,
    const float* __restrict__ aWhh,  const float* __restrict__ abih, const float* __restrict__ abhh,
    const float* __restrict__ gWih0, const float* __restrict__ gWihR,
    const float* __restrict__ gWhh,  const float* __restrict__ gbih, const float* __restrict__ gbhh) {
    const int stack = blockIdx.y;
    const int tid = threadIdx.x;
    const int b = blockIdx.x * 64 + tid;

    const float* inp  = stack ? gyro  : accel;
    const float* Wih0 = stack ? gWih0 : aWih0;
    const float* WihR = stack ? gWihR : aWihR;
    const float* Whh  = stack ? gWhh  : aWhh;
    const float* bih  = stack ? gbih  : abih;
    const float* bhh  = stack ? gbhh  : abhh;

    __shared__ __align__(16) float sWi[128 * 32];
    __shared__ __align__(16) float sWh[128 * 32];
    __shared__ float sB[128];
    __shared__ float cs[32 * 64];
    float* csrow = cs + tid;

#pragma unroll 1
    for (int l = 0; l < 5; l++) {
        __syncthreads();
        if (l == 0) {
            for (int idx = tid; idx < 128 * 32; idx += 64) {
                int k = idx & 31;
                sWi[idx] = (k < 3) ? Wih0[(idx >> 5) * 3 + k] : 0.f;
            }
        } else {
            const float* w = WihR + (size_t)(l - 1) * 4096;
            for (int idx = tid; idx < 4096; idx += 64) sWi[idx] = w[idx];
        }
        {
            const float* w = Whh + (size_t)l * 4096;
            for (int idx = tid; idx < 4096; idx += 64) sWh[idx] = w[idx];
        }
        for (int idx = tid; idx < 128; idx += 64) sB[idx] = bih[l * 128 + idx] + bhh[l * 128 + idx];
        __syncthreads();

        float* dst = (l == 4) ? (d_fcT + (size_t)stack * TT * HH * BB)
                              : d_scr[stack][l & 1];
        if (l == 0)
            run_layer<2, true>(b, inp, nullptr, dst, sWi, sWh, sB, csrow);
        else
            run_layer<16, false>(b, nullptr, d_scr[stack][(l - 1) & 1], dst, sWi, sWh, sB, csrow);
    }
}

// ---------------- FC head ----------------
__global__ void transpose_w(const float* __restrict__ w) {
    int idx = blockIdx.x * 256 + threadIdx.x;  // 1280*128 exact
    int k = idx >> 7, o = idx & 127;
    d_wt[idx] = w[o * 1280 + k];
}

// out[b][0..4] = fc2( relu( fc1(x_flat[b]) ) ), x_flat read from d_fcT ([k][b]).
__global__ void __launch_bounds__(256) fc_kernel(
    const float* __restrict__ fc1b, const float* __restrict__ fc2w,
    const float* __restrict__ fc2b, float* __restrict__ out) {
    __shared__ __align__(16) float As[16][64];    // A^T tile: [k][b]
    __shared__ __align__(16) float Ws[16 * 128];  // W^T tile: [k][o]
    __shared__ float H1[64][132];                 // relu(fc1) staging

    const int tid = threadIdx.x;
    const int b0 = blockIdx.x * 64;
    const int mi = tid & 15;   // b micro-group (4 rows)
    const int ni = tid >> 4;   // o micro-group (8 cols)

    ull acc[4][4];
#pragma unroll
    for (int i = 0; i < 4; i++)
#pragma unroll
        for (int p = 0; p < 4; p++) acc[i][p] = 0ull;

    const int akl = tid >> 4;
    const int ac4 = (tid & 15) * 4;

#pragma unroll 1
    for (int k0 = 0; k0 < 1280; k0 += 16) {
        __syncthreads();
        *(float4*)&As[akl][ac4] = *(const float4*)&d_fcT[(size_t)(k0 + akl) * BB + b0 + ac4];
        *(float4*)&Ws[tid * 4]        = *(const float4*)&d_wt[k0 * 128 + tid * 4];
        *(float4*)&Ws[1024 + tid * 4] = *(const float4*)&d_wt[k0 * 128 + 1024 + tid * 4];
        __syncthreads();
#pragma unroll
        for (int kl = 0; kl < 16; kl++) {
            float4 av = *(const float4*)&As[kl][mi * 4];
            ull ad0 = pk2(av.x, av.x), ad1 = pk2(av.y, av.y);
            ull ad2 = pk2(av.z, av.z), ad3 = pk2(av.w, av.w);
            const ulonglong2* wp = (const ulonglong2*)&Ws[kl * 128 + ni * 8];
            ulonglong2 w01 = wp[0], w23 = wp[1];
            acc[0][0] = fma2(ad0, w01.x, acc[0][0]); acc[0][1] = fma2(ad0, w01.y, acc[0][1]);
            acc[0][2] = fma2(ad0, w23.x, acc[0][2]); acc[0][3] = fma2(ad0, w23.y, acc[0][3]);
            acc[1][0] = fma2(ad1, w01.x, acc[1][0]); acc[1][1] = fma2(ad1, w01.y, acc[1][1]);
            acc[1][2] = fma2(ad1, w23.x, acc[1][2]); acc[1][3] = fma2(ad1, w23.y, acc[1][3]);
            acc[2][0] = fma2(ad2, w01.x, acc[2][0]); acc[2][1] = fma2(ad2, w01.y, acc[2][1]);
            acc[2][2] = fma2(ad2, w23.x, acc[2][2]); acc[2][3] = fma2(ad2, w23.y, acc[2][3]);
            acc[3][0] = fma2(ad3, w01.x, acc[3][0]); acc[3][1] = fma2(ad3, w01.y, acc[3][1]);
            acc[3][2] = fma2(ad3, w23.x, acc[3][2]); acc[3][3] = fma2(ad3, w23.y, acc[3][3]);
        }
    }
    __syncthreads();
#pragma unroll
    for (int i = 0; i < 4; i++) {
        int bl = mi * 4 + i;
#pragma unroll
        for (int p = 0; p < 4; p++) {
            int o = ni * 8 + 2 * p;
            float lo, hi; up2(acc[i][p], lo, hi);
            H1[bl][o]     = fmaxf(lo + fc1b[o], 0.f);
            H1[bl][o + 1] = fmaxf(hi + fc1b[o + 1], 0.f);
        }
    }
    __syncthreads();
    for (int idx = tid; idx < 320; idx += 256) {
        int bl = idx / 5, oo = idx - bl * 5;
        const float* w = fc2w + oo * 128;
        float s = fc2b[oo];
#pragma unroll 4
        for (int k = 0; k < 128; k++) s += H1[bl][k] * w[k];
        out[(size_t)(b0 + bl) * 5 + oo] = s;
    }
}

extern "C" void kernel_launch(void* const* d_in, const int* in_sizes, int n_in,
                              void* d_out, int out_size) {
    const float* accel = (const float*)d_in[0];
    const float* gyro  = (const float*)d_in[1];
    const float* aWih0 = (const float*)d_in[2];
    const float* aWihR = (const float*)d_in[3];
    const float* aWhh  = (const float*)d_in[4];
    const float* abih  = (const float*)d_in[5];
    const float* abhh  = (const float*)d_in[6];
    const float* gWih0 = (const float*)d_in[7];
    const float* gWihR = (const float*)d_in[8];
    const float* gWhh  = (const float*)d_in[9];
    const float* gbih  = (const float*)d_in[10];
    const float* gbhh  = (const float*)d_in[11];
    const float* fc1w  = (const float*)d_in[12];
    const float* fc1b  = (const float*)d_in[13];
    const float* fc2w  = (const float*)d_in[14];
    const float* fc2b  = (const float*)d_in[15];

    transpose_w<<<640, 256>>>(fc1w);

    dim3 grid(BB / 64, 2);
    lstm_kernel<<<grid, 64>>>(accel, gyro, aWih0, aWihR, aWhh, abih, abhh,
                              gWih0, gWihR, gWhh, gbih, gbhh);

    fc_kernel<<<BB / 64, 256>>>(fc1b, fc2w, fc2b, (float*)d_out);
}

// round 6
// speedup vs baseline: 1.0014x; 1.0014x over previous
#include <cuda_runtime.h>
#include <cstdint>

// GestureClassifier: 2 stacks x 5-layer LSTM (H=32, B=16384, T=20) + FC(1280->128 relu ->5)
// Strategy: one thread per batch element, f32x2 packed FMAs (reduction-dim packing),
// weights broadcast from shared, inter-layer handoff via [t][h][B] global scratch.

#define BB 16384
#define TT 20
#define HH 32

typedef unsigned long long ull;

static __device__ float d_scr[2][2][(size_t)TT * HH * BB];       // [stack][parity][t*32+h][b]
static __device__ float d_fcT[(size_t)2 * TT * HH * BB];         // [k=0..1279][b]  (A^T for FC)
static __device__ float d_wt[1280 * 128];                        // fc1_w transposed [k][o]

// ---------------- f32x2 helpers ----------------
__device__ __forceinline__ ull pk2(float lo, float hi) {
    ull r; asm("mov.b64 %0, {%1, %2};" : "=l"(r) : "f"(lo), "f"(hi)); return r;
}
__device__ __forceinline__ void up2(ull v, float& lo, float& hi) {
    asm("mov.b64 {%0, %1}, %2;" : "=f"(lo), "=f"(hi) : "l"(v));
}
__device__ __forceinline__ ull fma2(ull a, ull b, ull c) {
    ull d; asm("fma.rn.f32x2 %0, %1, %2, %3;" : "=l"(d) : "l"(a), "l"(b), "l"(c)); return d;
}
__device__ __forceinline__ ull add2(ull a, ull b) {
    ull d; asm("add.rn.f32x2 %0, %1, %2;" : "=l"(d) : "l"(a), "l"(b)); return d;
}

__device__ __forceinline__ float sigf(float x) {
    return __fdividef(1.f, 1.f + __expf(-x));
}
__device__ __forceinline__ float tanhfast(float x) {
    return __fdividef(2.f, 1.f + __expf(-2.f * x)) - 1.f;
}

// ---------------- LSTM ----------------
// gate preactivation for one gate row: bias + Wih_row . x + Whh_row . h
// NXP = number of f32x2 pairs of the input vector (16 for H=32 input, 2 for padded D=3)
template <int NXP>
__device__ __forceinline__ float gate_dot(const float* wi_row, const float* wh_row,
                                          const ull* xv, const ull* hv, float bias) {
    const ulonglong2* wi = reinterpret_cast<const ulonglong2*>(wi_row);
    const ulonglong2* wh = reinterpret_cast<const ulonglong2*>(wh_row);
    ull a0 = 0, a1 = 0, a2 = 0, a3 = 0;
#pragma unroll
    for (int q = 0; q < NXP / 2; q++) {
        ulonglong2 w = wi[q];
        a0 = fma2(w.x, xv[2 * q], a0);
        a1 = fma2(w.y, xv[2 * q + 1], a1);
    }
#pragma unroll
    for (int q = 0; q < 8; q++) {
        ulonglong2 w = wh[q];
        a2 = fma2(w.x, hv[2 * q], a2);
        a3 = fma2(w.y, hv[2 * q + 1], a3);
    }
    ull s = add2(add2(a0, a2), add2(a1, a3));
    float lo, hi; up2(s, lo, hi);
    return bias + lo + hi;
}

// One LSTM layer for one batch element.
//  FIRST: x from raw input [b][t][3];  else: x from src[t*32+k][b]
//  dst[t*32+j][b] receives h; h for step t is reloaded from dst[t-1] (same thread).
template <int NXP, bool FIRST>
__device__ __forceinline__ void run_layer(int b, const float* __restrict__ in3,
                                          const float* __restrict__ src,
                                          float* __restrict__ dst,
                                          const float* sWi, const float* sWh,
                                          const float* sB, float* csrow) {
    ull xv[16], hv[16];
#pragma unroll
    for (int p = 0; p < 16; p++) { xv[p] = 0ull; hv[p] = 0ull; }
#pragma unroll
    for (int j = 0; j < 32; j++) csrow[j * 64] = 0.f;

#pragma unroll 1
    for (int t = 0; t < TT; t++) {
        if constexpr (FIRST) {
            const float* p = in3 + ((size_t)b * TT + t) * 3;
            xv[0] = pk2(p[0], p[1]);
            xv[1] = pk2(p[2], 0.f);
        } else {
            const float* s0 = src + (size_t)t * HH * BB + b;
#pragma unroll
            for (int p = 0; p < 16; p++)
                xv[p] = pk2(s0[(size_t)(2 * p) * BB], s0[(size_t)(2 * p + 1) * BB]);
        }
        if (t > 0) {
            const float* h0 = dst + (size_t)(t - 1) * HH * BB + b;
#pragma unroll
            for (int p = 0; p < 16; p++)
                hv[p] = pk2(h0[(size_t)(2 * p) * BB], h0[(size_t)(2 * p + 1) * BB]);
        }
        float* o0 = dst + (size_t)t * HH * BB + b;
#pragma unroll 2
        for (int j = 0; j < 32; j++) {
            float gi = gate_dot<NXP>(sWi + j * 32,          sWh + j * 32,          xv, hv, sB[j]);
            float gf = gate_dot<NXP>(sWi + (32 + j) * 32,   sWh + (32 + j) * 32,   xv, hv, sB[32 + j]);
            float gg = gate_dot<NXP>(sWi + (64 + j) * 32,   sWh + (64 + j) * 32,   xv, hv, sB[64 + j]);
            float go = gate_dot<NXP>(sWi + (96 + j) * 32,   sWh + (96 + j) * 32,   xv, hv, sB[96 + j]);
            float ig = sigf(gi);
            float fg = sigf(gf);
            float gv = tanhfast(gg);
            float og = sigf(go);
            float c = fg * csrow[j * 64] + ig * gv;
            csrow[j * 64] = c;
            o0[(size_t)j * BB] = og * tanhfast(c);
        }
    }
}

__global__ void __launch_bounds__(64) lstm_kernel(
    const float* __restrict__ accel, const float* __restrict__ gyro,
    const float* __restrict__ aWih0, const float* __restrict__ aWihR,
    const float* __restrict__ aWhh,  const float* __restrict__ abih, const float* __restrict__ abhh,
    const float* __restrict__ gWih0, const float* __restrict__ gWihR,
    const float* __restrict__ gWhh,  const float* __restrict__ gbih, const float* __restrict__ gbhh) {
    const int stack = blockIdx.y;
    const int tid = threadIdx.x;
    const int b = blockIdx.x * 64 + tid;

    const float* inp  = stack ? gyro  : accel;
    const float* Wih0 = stack ? gWih0 : aWih0;
    const float* WihR = stack ? gWihR : aWihR;
    const float* Whh  = stack ? gWhh  : aWhh;
    const float* bih  = stack ? gbih  : abih;
    const float* bhh  = stack ? gbhh  : abhh;

    __shared__ __align__(16) float sWi[128 * 32];
    __shared__ __align__(16) float sWh[128 * 32];
    __shared__ float sB[128];
    __shared__ float cs[32 * 64];
    float* csrow = cs + tid;

#pragma unroll 1
    for (int l = 0; l < 5; l++) {
        __syncthreads();
        if (l == 0) {
            for (int idx = tid; idx < 128 * 32; idx += 64) {
                int k = idx & 31;
                sWi[idx] = (k < 3) ? Wih0[(idx >> 5) * 3 + k] : 0.f;
            }
        } else {
            const float* w = WihR + (size_t)(l - 1) * 4096;
            for (int idx = tid; idx < 4096; idx += 64) sWi[idx] = w[idx];
        }
        {
            const float* w = Whh + (size_t)l * 4096;
            for (int idx = tid; idx < 4096; idx += 64) sWh[idx] = w[idx];
        }
        for (int idx = tid; idx < 128; idx += 64) sB[idx] = bih[l * 128 + idx] + bhh[l * 128 + idx];
        __syncthreads();

        float* dst = (l == 4) ? (d_fcT + (size_t)stack * TT * HH * BB)
                              : d_scr[stack][l & 1];
        if (l == 0)
            run_layer<2, true>(b, inp, nullptr, dst, sWi, sWh, sB, csrow);
        else
            run_layer<16, false>(b, nullptr, d_scr[stack][(l - 1) & 1], dst, sWi, sWh, sB, csrow);
    }
}

// ---------------- FC head ----------------
__global__ void transpose_w(const float* __restrict__ w) {
    int idx = blockIdx.x * 256 + threadIdx.x;  // 1280*128 exact
    int k = idx >> 7, o = idx & 127;
    d_wt[idx] = w[o * 1280 + k];
}

// out[b][0..4] = fc2( relu( fc1(x_flat[b]) ) ), x_flat read from d_fcT ([k][b]).
__global__ void __launch_bounds__(256) fc_kernel(
    const float* __restrict__ fc1b, const float* __restrict__ fc2w,
    const float* __restrict__ fc2b, float* __restrict__ out) {
    __shared__ __align__(16) float As[16][64];    // A^T tile: [k][b]
    __shared__ __align__(16) float Ws[16 * 128];  // W^T tile: [k][o]
    __shared__ float H1[64][132];                 // relu(fc1) staging

    const int tid = threadIdx.x;
    const int b0 = blockIdx.x * 64;
    const int mi = tid & 15;   // b micro-group (4 rows)
    const int ni = tid >> 4;   // o micro-group (8 cols)

    ull acc[4][4];
#pragma unroll
    for (int i = 0; i < 4; i++)
#pragma unroll
        for (int p = 0; p < 4; p++) acc[i][p] = 0ull;

    const int akl = tid >> 4;
    const int ac4 = (tid & 15) * 4;

#pragma unroll 1
    for (int k0 = 0; k0 < 1280; k0 += 16) {
        __syncthreads();
        *(float4*)&As[akl][ac4] = *(const float4*)&d_fcT[(size_t)(k0 + akl) * BB + b0 + ac4];
        *(float4*)&Ws[tid * 4]        = *(const float4*)&d_wt[k0 * 128 + tid * 4];
        *(float4*)&Ws[1024 + tid * 4] = *(const float4*)&d_wt[k0 * 128 + 1024 + tid * 4];
        __syncthreads();
#pragma unroll
        for (int kl = 0; kl < 16; kl++) {
            float4 av = *(const float4*)&As[kl][mi * 4];
            ull ad0 = pk2(av.x, av.x), ad1 = pk2(av.y, av.y);
            ull ad2 = pk2(av.z, av.z), ad3 = pk2(av.w, av.w);
            const ulonglong2* wp = (const ulonglong2*)&Ws[kl * 128 + ni * 8];
            ulonglong2 w01 = wp[0], w23 = wp[1];
            acc[0][0] = fma2(ad0, w01.x, acc[0][0]); acc[0][1] = fma2(ad0, w01.y, acc[0][1]);
            acc[0][2] = fma2(ad0, w23.x, acc[0][2]); acc[0][3] = fma2(ad0, w23.y, acc[0][3]);
            acc[1][0] = fma2(ad1, w01.x, acc[1][0]); acc[1][1] = fma2(ad1, w01.y, acc[1][1]);
            acc[1][2] = fma2(ad1, w23.x, acc[1][2]); acc[1][3] = fma2(ad1, w23.y, acc[1][3]);
            acc[2][0] = fma2(ad2, w01.x, acc[2][0]); acc[2][1] = fma2(ad2, w01.y, acc[2][1]);
            acc[2][2] = fma2(ad2, w23.x, acc[2][2]); acc[2][3] = fma2(ad2, w23.y, acc[2][3]);
            acc[3][0] = fma2(ad3, w01.x, acc[3][0]); acc[3][1] = fma2(ad3, w01.y, acc[3][1]);
            acc[3][2] = fma2(ad3, w23.x, acc[3][2]); acc[3][3] = fma2(ad3, w23.y, acc[3][3]);
        }
    }
    __syncthreads();
#pragma unroll
    for (int i = 0; i < 4; i++) {
        int bl = mi * 4 + i;
#pragma unroll
        for (int p = 0; p < 4; p++) {
            int o = ni * 8 + 2 * p;
            float lo, hi; up2(acc[i][p], lo, hi);
            H1[bl][o]     = fmaxf(lo + fc1b[o], 0.f);
            H1[bl][o + 1] = fmaxf(hi + fc1b[o + 1], 0.f);
        }
    }
    __syncthreads();
    for (int idx = tid; idx < 320; idx += 256) {
        int bl = idx / 5, oo = idx - bl * 5;
        const float* w = fc2w + oo * 128;
        float s = fc2b[oo];
#pragma unroll 4
        for (int k = 0; k < 128; k++) s += H1[bl][k] * w[k];
        out[(size_t)(b0 + bl) * 5 + oo] = s;
    }
}

extern "C" void kernel_launch(void* const* d_in, const int* in_sizes, int n_in,
                              void* d_out, int out_size) {
    const float* accel = (const float*)d_in[0];
    const float* gyro  = (const float*)d_in[1];
    const float* aWih0 = (const float*)d_in[2];
    const float* aWihR = (const float*)d_in[3];
    const float* aWhh  = (const float*)d_in[4];
    const float* abih  = (const float*)d_in[5];
    const float* abhh  = (const float*)d_in[6];
    const float* gWih0 = (const float*)d_in[7];
    const float* gWihR = (const float*)d_in[8];
    const float* gWhh  = (const float*)d_in[9];
    const float* gbih  = (const float*)d_in[10];
    const float* gbhh  = (const float*)d_in[11];
    const float* fc1w  = (const float*)d_in[12];
    const float* fc1b  = (const float*)d_in[13];
    const float* fc2w  = (const float*)d_in[14];
    const float* fc2b  = (const float*)d_in[15];

    transpose_w<<<640, 256>>>(fc1w);

    dim3 grid(BB / 64, 2);
    lstm_kernel<<<grid, 64>>>(accel, gyro, aWih0, aWihR, aWhh, abih, abhh,
                              gWih0, gWihR, gWhh, gbih, gbhh);

    fc_kernel<<<BB / 64, 256>>>(fc1b, fc2w, fc2b, (float*)d_out);
}